// round 13
// baseline (speedup 1.0000x reference)
#include <cuda_runtime.h>
#include <cuda_fp16.h>
#include <math.h>

// X [T=16384, H=2880] f32; W [E=128, H=2880] f32; bias [E=128] f32
// d_out f32: [0,T*4) softmax vals | [T*4,T*8) indices | [T*8,..) logits [T,E]
//
// Kernel A (wcvt): W f32 -> fp16, pre-swizzled tile layout (R12-proven).
// Kernel B (gemm): BM=64 x BN=128, 512 threads (16 warps x 16Mx32N),
//   2 CTAs/SM (87 KB smem, <=64 regs). Single-barrier pipeline:
//   X cp.async f32 ring (4) + in-kernel cvt; B cp.async fp16 direct.
//   Epilogue: bias, logits, top-8, candidate records (EPS=2.5e-3).
// Kernel C (refine): R9-proven candidate refinement, grid 2048.

#define NTHREADS 512
#define BM 64
#define BN 128
#define LPAD 129
#define AMBIG_EPS 2.5e-3f

#define SM_BIAS   128
#define SM_XSTG   1024
#define XSLOT_B   (64 * 144)                  // f32 stage: 64 rows x 144B = 9216
#define SM_TILES  (SM_XSTG + 4 * XSLOT_B)     // 37888
#define TILE_A    4096                        // fp16 A: 64 rows x 64B
#define TILE_Bb   8192                        // fp16 B: 128 rows x 64B
#define FBUF_B    (TILE_A + TILE_Bb)          // 12288
#define SMEM_TOTAL (SM_TILES + 4 * FBUF_B)    // 87040

__device__ int  g_count;
__device__ int  g_done;
__device__ int4 g_rec[16384];                         // {token, idx0..3, idx4..7, mode}
__device__ __align__(16) unsigned char g_wfp16[90 * 8192];  // 737,280 B

extern __shared__ __align__(1024) char smem[];

__device__ __forceinline__ unsigned int smem_u32(const void* p) {
    unsigned int a;
    asm("{ .reg .u64 t; cvta.to.shared.u64 t, %1; cvt.u32.u64 %0, t; }"
        : "=r"(a) : "l"(p));
    return a;
}
__device__ __forceinline__ void cp16(unsigned int dst, const void* src) {
    asm volatile("cp.async.cg.shared.global [%0], [%1], 16;"
                 :: "r"(dst), "l"(src));
}
__device__ __forceinline__ void ldm4(unsigned int* r, unsigned int addr) {
    asm volatile("ldmatrix.sync.aligned.m8n8.x4.shared.b16 {%0,%1,%2,%3}, [%4];"
                 : "=r"(r[0]), "=r"(r[1]), "=r"(r[2]), "=r"(r[3]) : "r"(addr));
}
__device__ __forceinline__ void mma16816(float* c, const unsigned int* a,
                                         unsigned int b0, unsigned int b1) {
    asm volatile(
        "mma.sync.aligned.m16n8k16.row.col.f32.f16.f16.f32 "
        "{%0,%1,%2,%3}, {%4,%5,%6,%7}, {%8,%9}, {%0,%1,%2,%3};"
        : "+f"(c[0]), "+f"(c[1]), "+f"(c[2]), "+f"(c[3])
        : "r"(a[0]), "r"(a[1]), "r"(a[2]), "r"(a[3]), "r"(b0), "r"(b1));
}
__device__ __forceinline__ uint4 cvt8h(float4 v0, float4 v1) {
    __half2 h0 = __floats2half2_rn(v0.x, v0.y);
    __half2 h1 = __floats2half2_rn(v0.z, v0.w);
    __half2 h2 = __floats2half2_rn(v1.x, v1.y);
    __half2 h3 = __floats2half2_rn(v1.z, v1.w);
    return make_uint4(*(unsigned int*)&h0, *(unsigned int*)&h1,
                      *(unsigned int*)&h2, *(unsigned int*)&h3);
}

// ---------------- W pre-conversion (unchanged from R12) ----------------
__global__ void wcvt_kernel(const float* __restrict__ W, int H) {
    const int idx = blockIdx.x * 256 + threadIdx.x;
    const int nchunks = (H / 32) * 512;
    if (idx >= nchunks) return;
    const int t = idx >> 9;
    const int rc = idx & 511;
    const int r = rc >> 2;
    const int p = rc & 3;
    const int c = p ^ ((r >> 1) & 3);
    const float4* src = (const float4*)(W + (size_t)r * H + t * 32 + c * 8);
    *(uint4*)(g_wfp16 + (size_t)idx * 16) = cvt8h(src[0], src[1]);
}

__global__ __launch_bounds__(NTHREADS, 2)
void gemm_kernel(const float* __restrict__ X,
                 const float* __restrict__ bias,
                 float* __restrict__ out_vals,
                 float* __restrict__ out_idx,
                 float* __restrict__ out_logits,
                 int T, int H)
{
    const int tid  = threadIdx.x;
    const int wid  = tid >> 5;
    const int lane = tid & 31;
    const int rowBase = blockIdx.x * BM;
    const unsigned int sb = smem_u32(smem);

    const int m_base = (wid >> 2) * 16;     // 4 m-warps x 16 rows
    const int n_base = (wid & 3) * 32;      // 4 n-warps x 32 cols

    if (tid < BN) ((float*)(smem + SM_BIAS))[tid] = bias[tid];

    const int nst = H / 32;   // 90

    // ---- X cp.async mapping: 64 rows x 8 chunks = 512 -> 1 chunk/thread ----
    const int xr0 = tid >> 3;               // 0..63
    const int xc  = tid & 7;
    const float* xsrc = X + (size_t)(rowBase + xr0) * H + xc * 4;
    const unsigned int xd = sb + SM_XSTG + (unsigned int)(xr0 * 144 + xc * 16);

    // ---- X cvt mapping: threads 0..255, 8 f32 each ----
    const int lrow = tid >> 2;              // 0..63 for tid<256
    const int lq   = tid & 3;
    const unsigned int xstg_rd = (unsigned int)(lrow * 144 + lq * 32);
    const unsigned int fst = (unsigned int)(lrow * 64) +
                             ((unsigned int)(lq ^ ((lrow >> 1) & 3)) << 4);

    // ---- B cp.async mapping: 8192B/stage = 512 chunks -> 1/thread ----
    const unsigned int bdst = sb + SM_TILES + TILE_A + (unsigned int)tid * 16;
    const unsigned char* bsrc = g_wfp16 + (size_t)tid * 16;

    // ---- ldmatrix per-lane pieces ----
    const int arow = m_base + ((lane >> 3) & 1) * 8 + (lane & 7);
    const int brow0 = n_base + (lane >> 4) * 8 + (lane & 7);
    const unsigned int acol = (unsigned int)(lane >> 4);
    const unsigned int bcol = (unsigned int)((lane >> 3) & 1);

    const unsigned int aoff = (unsigned int)(arow * 64);
    const unsigned int axor = (unsigned int)((arow >> 1) & 3);
    unsigned int boff[2], bxor[2];
    #pragma unroll
    for (int nt = 0; nt < 2; nt++) {
        const int r = brow0 + nt * 16;
        boff[nt] = (unsigned int)(r * 64);
        bxor[nt] = (unsigned int)((r >> 1) & 3);
    }

    const unsigned int ftiles = sb + SM_TILES;

    float acc[4][4];
    #pragma unroll
    for (int n8 = 0; n8 < 4; n8++)
        #pragma unroll
        for (int i = 0; i < 4; i++) acc[n8][i] = 0.0f;

    // ---- prologue: G0={X0,B0} G1={X1,B1} G2={X2} G3={X3} ----
    #pragma unroll
    for (int s = 0; s < 4; s++) {
        cp16(xd + (unsigned int)(s * XSLOT_B), xsrc + s * 32);
        if (s < 2)
            cp16(bdst + (unsigned int)(s * FBUF_B), bsrc + (size_t)s * 8192);
        asm volatile("cp.async.commit_group;");
    }

    asm volatile("cp.async.wait_group 3;");
    __syncthreads();
    if (tid < 256) {   // cvt X0 -> fbuf0 A
        const char* xs = smem + SM_XSTG;
        float4 x0 = *(const float4*)(xs + xstg_rd);
        float4 x1 = *(const float4*)(xs + xstg_rd + 16);
        *(uint4*)(smem + SM_TILES + fst) = cvt8h(x0, x1);
    }
    asm volatile("cp.async.wait_group 2;");
    __syncthreads();
    if (tid < 256) {   // cvt X1 -> fbuf1 A
        const char* xs = smem + SM_XSTG + XSLOT_B;
        float4 x0 = *(const float4*)(xs + xstg_rd);
        float4 x1 = *(const float4*)(xs + xstg_rd + 16);
        *(uint4*)(smem + SM_TILES + FBUF_B + fst) = cvt8h(x0, x1);
    }
    __syncthreads();

    for (int t = 0; t < nst; t++) {
        if (t + 2 < nst) {
            // issue B(t+2) into fbuf[(t+2)&3]; X(t+4) into xring[(t+4)&3]
            cp16(bdst + (unsigned int)(((t + 2) & 3) * FBUF_B),
                 bsrc + (size_t)(t + 2) * 8192);
            if (t + 4 < nst)
                cp16(xd + (unsigned int)(((t + 4) & 3) * XSLOT_B),
                     xsrc + (t + 4) * 32);
            asm volatile("cp.async.commit_group;");
            asm volatile("cp.async.wait_group 2;");
            __syncthreads();   // X(t+2), B(t) visible; fbuf[(t+2)&3] A free

            // cvt X(t+2) -> fbuf[(t+2)&3] A (overlaps MMA below)
            if (tid < 256) {
                const char* xs = smem + SM_XSTG + ((t + 2) & 3) * XSLOT_B;
                float4 x0 = *(const float4*)(xs + xstg_rd);
                float4 x1 = *(const float4*)(xs + xstg_rd + 16);
                char* fb = smem + SM_TILES + ((t + 2) & 3) * FBUF_B;
                *(uint4*)(fb + fst) = cvt8h(x0, x1);
            }
        } else if (t + 2 == nst) {
            asm volatile("cp.async.wait_group 1;");
            __syncthreads();
        } else {
            asm volatile("cp.async.wait_group 0;");
            __syncthreads();
        }

        // ---- MMA(t) on fbuf[t&3] ----
        const unsigned int base = ftiles + (unsigned int)(t & 3) * FBUF_B;
        #pragma unroll
        for (int kk = 0; kk < 2; kk++) {
            unsigned int ah[4], bh[2][4];
            {
                const unsigned int c = (unsigned int)(kk * 2) + acol;
                ldm4(ah, base + aoff + ((c ^ axor) << 4));
            }
            #pragma unroll
            for (int nt = 0; nt < 2; nt++) {
                const unsigned int c = (unsigned int)(kk * 2) + bcol;
                ldm4(bh[nt], base + TILE_A + boff[nt] + ((c ^ bxor[nt]) << 4));
            }
            #pragma unroll
            for (int nt = 0; nt < 2; nt++)
                #pragma unroll
                for (int p = 0; p < 2; p++)
                    mma16816(acc[nt * 2 + p], ah,
                             bh[nt][p * 2], bh[nt][p * 2 + 1]);
        }
    }
    __syncthreads();   // rings free; reuse as logits staging

    // ---------------- Epilogue ----------------
    float* Ls = (float*)(smem + SM_XSTG);             // [64][LPAD]
    const float* bsm = (const float*)(smem + SM_BIAS);

    {
        const int r1 = m_base + (lane >> 2);
        #pragma unroll
        for (int n8 = 0; n8 < 4; n8++) {
            const int c = n_base + n8 * 8 + (lane & 3) * 2;
            const float b0 = bsm[c], b1 = bsm[c + 1];
            Ls[r1 * LPAD + c]           = acc[n8][0] + b0;
            Ls[r1 * LPAD + c + 1]       = acc[n8][1] + b1;
            Ls[(r1 + 8) * LPAD + c]     = acc[n8][2] + b0;
            Ls[(r1 + 8) * LPAD + c + 1] = acc[n8][3] + b1;
        }
    }
    __syncthreads();

    // logits to gmem: 64 rows x 32 float4 = 2048
    #pragma unroll
    for (int i = 0; i < 4; i++) {
        const int idx = tid + NTHREADS * i;
        const int row = idx >> 5;
        const int c4  = idx & 31;
        float4 v;
        v.x = Ls[row * LPAD + c4 * 4 + 0];
        v.y = Ls[row * LPAD + c4 * 4 + 1];
        v.z = Ls[row * LPAD + c4 * 4 + 2];
        v.w = Ls[row * LPAD + c4 * 4 + 3];
        *(float4*)&out_logits[(size_t)(rowBase + row) * BN + c4 * 4] = v;
    }

    // top-8 scan + provisional outputs + candidate records
    if (tid < BM) {
        const int token = rowBase + tid;
        const float* row = &Ls[tid * LPAD];
        float tv[8];
        int   ti[8];
        #pragma unroll
        for (int s = 0; s < 8; s++) { tv[s] = -1e30f; ti[s] = 0; }
        for (int e = 0; e < BN; e++) {
            float val = row[e];
            if (val > tv[7]) {
                tv[7] = val; ti[7] = e;
                #pragma unroll
                for (int s = 7; s > 0; s--) {
                    if (tv[s] > tv[s - 1]) {     // strict >: earlier index wins
                        float fv = tv[s]; tv[s] = tv[s-1]; tv[s-1] = fv;
                        int   fi = ti[s]; ti[s] = ti[s-1]; ti[s-1] = fi;
                    }
                }
            }
        }
        bool ambig = (tv[0] - tv[1] < AMBIG_EPS) |
                     (tv[1] - tv[2] < AMBIG_EPS) |
                     (tv[2] - tv[3] < AMBIG_EPS) |
                     (tv[3] - tv[4] < AMBIG_EPS);
        if (ambig) {
            const int mode = (tv[3] - tv[7] < AMBIG_EPS) ? 1 : 0;
            const int lo = ti[0] | (ti[1] << 8) | (ti[2] << 16) | (ti[3] << 24);
            const int hi = ti[4] | (ti[5] << 8) | (ti[6] << 16) | (ti[7] << 24);
            int p = atomicAdd(&g_count, 1);
            g_rec[p] = make_int4(token, lo, hi, mode);
        }
        const float mx = tv[0];
        float e0 = expf(tv[0] - mx);
        float e1 = expf(tv[1] - mx);
        float e2 = expf(tv[2] - mx);
        float e3 = expf(tv[3] - mx);
        const float inv = 1.0f / (e0 + e1 + e2 + e3);
        out_vals[(size_t)token * 4 + 0] = e0 * inv;
        out_vals[(size_t)token * 4 + 1] = e1 * inv;
        out_vals[(size_t)token * 4 + 2] = e2 * inv;
        out_vals[(size_t)token * 4 + 3] = e3 * inv;
        out_idx[(size_t)token * 4 + 0] = (float)ti[0];
        out_idx[(size_t)token * 4 + 1] = (float)ti[1];
        out_idx[(size_t)token * 4 + 2] = (float)ti[2];
        out_idx[(size_t)token * 4 + 3] = (float)ti[3];
    }
}

// ---------------- Candidate refinement (R9-proven config) ----------------
__global__ __launch_bounds__(256)
void refine_kernel(const float* __restrict__ X,
                   const float* __restrict__ W,
                   const float* __restrict__ bias,
                   float* __restrict__ out_vals,
                   float* __restrict__ out_idx,
                   int T, int H)
{
    const int cnt = *(volatile int*)&g_count;
    __shared__ double s_partial[256];
    __shared__ double s_logit[128];
    __shared__ double s_l8[8];
    __shared__ int    s_i8[8];

    const int tid  = threadIdx.x;
    const int wid  = tid >> 5;
    const int lane = tid & 31;

    for (int it = blockIdx.x; it < cnt; it += gridDim.x) {
        const int4 rec = g_rec[it];
        const int token = rec.x;

        if (rec.w == 0) {
            const int packed = (wid < 4) ? rec.y : rec.z;
            const int eidx = (packed >> ((wid & 3) * 8)) & 0xFF;

            const float* xr = X + (size_t)token * H;
            const float* wr = W + (size_t)eidx * H;

            float s = 0.f, c = 0.f;
            const int n32 = H >> 5;
            for (int i = 0; i < n32; i++) {
                const int k = i * 32 + lane;
                float a = xr[k], b = wr[k];
                float p  = a * b;
                float pe = fmaf(a, b, -p);
                float t2 = s + p;
                float z  = t2 - s;
                float er = (s - (t2 - z)) + (p - z);
                s = t2;
                c += er + pe;
            }
            double part = (double)s + (double)c;
            #pragma unroll
            for (int off = 16; off > 0; off >>= 1)
                part += __shfl_xor_sync(0xFFFFFFFFu, part, off);
            if (lane == 0) {
                s_l8[wid] = part + (double)bias[eidx];
                s_i8[wid] = eidx;
            }
            __syncthreads();

            if (tid == 0) {
                double v[8]; int ix[8];
                #pragma unroll
                for (int j = 0; j < 8; j++) { v[j] = s_l8[j]; ix[j] = s_i8[j]; }
                #pragma unroll
                for (int a2 = 0; a2 < 4; a2++) {
                    int best = a2;
                    #pragma unroll
                    for (int b2 = a2 + 1; b2 < 8; b2++) {
                        if (v[b2] > v[best] ||
                            (v[b2] == v[best] && ix[b2] < ix[best])) best = b2;
                    }
                    double fv = v[a2]; v[a2] = v[best]; v[best] = fv;
                    int    fi = ix[a2]; ix[a2] = ix[best]; ix[best] = fi;
                }
                float v0 = (float)v[0], v1 = (float)v[1],
                      v2 = (float)v[2], v3 = (float)v[3];
                float e0 = expf(v0 - v0);
                float e1 = expf(v1 - v0);
                float e2 = expf(v2 - v0);
                float e3 = expf(v3 - v0);
                float inv = 1.0f / (e0 + e1 + e2 + e3);
                out_vals[(size_t)token * 4 + 0] = e0 * inv;
                out_vals[(size_t)token * 4 + 1] = e1 * inv;
                out_vals[(size_t)token * 4 + 2] = e2 * inv;
                out_vals[(size_t)token * 4 + 3] = e3 * inv;
                out_idx[(size_t)token * 4 + 0] = (float)ix[0];
                out_idx[(size_t)token * 4 + 1] = (float)ix[1];
                out_idx[(size_t)token * 4 + 2] = (float)ix[2];
                out_idx[(size_t)token * 4 + 3] = (float)ix[3];
            }
            __syncthreads();
        } else {
            const int e = tid >> 1;
            const int h = tid & 1;
            const int half = H >> 1;
            const int nq = half >> 2;
            const float4* xr = (const float4*)(X + (size_t)token * H + (size_t)h * half);
            const float4* wr = (const float4*)(W + (size_t)e * H + (size_t)h * half);

            float s[4] = {0.f, 0.f, 0.f, 0.f};
            float c[4] = {0.f, 0.f, 0.f, 0.f};
            for (int i = 0; i < nq; i++) {
                float4 xvv = xr[i];
                float4 wvv = wr[i];
                float a4[4] = {xvv.x, xvv.y, xvv.z, xvv.w};
                float b4[4] = {wvv.x, wvv.y, wvv.z, wvv.w};
                #pragma unroll
                for (int l = 0; l < 4; l++) {
                    float p  = a4[l] * b4[l];
                    float pe = fmaf(a4[l], b4[l], -p);
                    float t2 = s[l] + p;
                    float z  = t2 - s[l];
                    float er = (s[l] - (t2 - z)) + (p - z);
                    s[l] = t2;
                    c[l] += er + pe;
                }
            }
            double tot = 0.0;
            #pragma unroll
            for (int l = 0; l < 4; l++) tot += (double)s[l] + (double)c[l];
            s_partial[tid] = tot;
            __syncthreads();

            if (h == 0)
                s_logit[e] = s_partial[2 * e] + s_partial[2 * e + 1] + (double)bias[e];
            __syncthreads();

            if (tid == 0) {
                double tv[4] = {-1e300, -1e300, -1e300, -1e300};
                int    ti[4] = {0, 0, 0, 0};
                for (int k = 0; k < 128; k++) {
                    double val = s_logit[k];
                    if (val > tv[3]) {
                        tv[3] = val; ti[3] = k;
                        #pragma unroll
                        for (int s2 = 3; s2 > 0; s2--) {
                            if (tv[s2] > tv[s2 - 1]) {
                                double fv = tv[s2]; tv[s2] = tv[s2-1]; tv[s2-1] = fv;
                                int    fi = ti[s2]; ti[s2] = ti[s2-1]; ti[s2-1] = fi;
                            }
                        }
                    }
                }
                float v0 = (float)tv[0], v1 = (float)tv[1],
                      v2 = (float)tv[2], v3 = (float)tv[3];
                float e0 = expf(v0 - v0);
                float e1 = expf(v1 - v0);
                float e2 = expf(v2 - v0);
                float e3 = expf(v3 - v0);
                float inv = 1.0f / (e0 + e1 + e2 + e3);
                out_vals[(size_t)token * 4 + 0] = e0 * inv;
                out_vals[(size_t)token * 4 + 1] = e1 * inv;
                out_vals[(size_t)token * 4 + 2] = e2 * inv;
                out_vals[(size_t)token * 4 + 3] = e3 * inv;
                out_idx[(size_t)token * 4 + 0] = (float)ti[0];
                out_idx[(size_t)token * 4 + 1] = (float)ti[1];
                out_idx[(size_t)token * 4 + 2] = (float)ti[2];
                out_idx[(size_t)token * 4 + 3] = (float)ti[3];
            }
            __syncthreads();
        }
    }

    // last finishing block resets the worklist for the next graph replay
    __syncthreads();
    if (threadIdx.x == 0) {
        const int d = atomicAdd(&g_done, 1);
        if (d == (int)gridDim.x - 1) {
            g_count = 0;
            g_done  = 0;
        }
    }
}

extern "C" void kernel_launch(void* const* d_in, const int* in_sizes, int n_in,
                              void* d_out, int out_size)
{
    const float* X    = (const float*)d_in[0];
    const float* W    = (const float*)d_in[1];
    const float* bias = (const float*)d_in[2];

    const int E = in_sizes[2];          // 128
    const int H = in_sizes[1] / E;      // 2880
    const int T = in_sizes[0] / H;      // 16384

    float* out        = (float*)d_out;
    float* out_vals   = out;
    float* out_idx    = out + (size_t)T * 4;
    float* out_logits = out + (size_t)T * 8;

    cudaFuncSetAttribute(gemm_kernel,
                         cudaFuncAttributeMaxDynamicSharedMemorySize,
                         SMEM_TOTAL);

    const int nchunks = (H / 32) * 512;            // 46080
    wcvt_kernel<<<(nchunks + 255) / 256, 256>>>(W, H);
    gemm_kernel<<<T / BM, NTHREADS, SMEM_TOTAL>>>(
        X, bias, out_vals, out_idx, out_logits, T, H);
    refine_kernel<<<2048, 256>>>(X, W, bias, out_vals, out_idx, T, H);
}

// round 14
// speedup vs baseline: 1.0110x; 1.0110x over previous
#include <cuda_runtime.h>
#include <cuda_fp16.h>
#include <math.h>

// X [T=16384, H=2880] f32; W [E=128, H=2880] f32; bias [E=128] f32
// d_out f32: [0,T*4) softmax vals | [T*4,T*8) indices | [T*8,..) logits [T,E]
//
// Kernel A (wcvt): W f32 -> fp16, pre-swizzled tile layout (R12-proven).
// Kernel B (gemm): BM=128 x BN=128, 512 threads. NO X smem ring:
//   X LDG f32 -> regs -> cvt -> STS fp16 (smem traffic 138->88 KB/stage).
//   B: cp.async fp16 direct from g_wfp16. 4-deep fbuf ring, 1 barrier/stage.
//   Epilogue: bias, logits, top-8, candidate records (EPS=2.5e-3).
// Kernel C (refine): candidate refinement, grid 2048, 2 interleaved chains.

#define NTHREADS 512
#define BM 128
#define BN 128
#define LPAD 129
#define AMBIG_EPS 2.5e-3f

#define SM_BIAS   128
#define SM_TILES  1024
#define TILE_A    8192                        // fp16 A: 128 rows x 64B
#define TILE_Bb   8192                        // fp16 B: 128 rows x 64B
#define FBUF_B    (TILE_A + TILE_Bb)          // 16384
#define SMEM_TOTAL (SM_TILES + BM * LPAD * 4) // 67072 (> 1024 + 4*16384)

__device__ int  g_count;
__device__ int  g_done;
__device__ int4 g_rec[16384];                         // {token, idx0..3, idx4..7, mode}
__device__ __align__(16) unsigned char g_wfp16[90 * 8192];  // 737,280 B

extern __shared__ __align__(1024) char smem[];

__device__ __forceinline__ unsigned int smem_u32(const void* p) {
    unsigned int a;
    asm("{ .reg .u64 t; cvta.to.shared.u64 t, %1; cvt.u32.u64 %0, t; }"
        : "=r"(a) : "l"(p));
    return a;
}
__device__ __forceinline__ void cp16(unsigned int dst, const void* src) {
    asm volatile("cp.async.cg.shared.global [%0], [%1], 16;"
                 :: "r"(dst), "l"(src));
}
__device__ __forceinline__ void ldm4(unsigned int* r, unsigned int addr) {
    asm volatile("ldmatrix.sync.aligned.m8n8.x4.shared.b16 {%0,%1,%2,%3}, [%4];"
                 : "=r"(r[0]), "=r"(r[1]), "=r"(r[2]), "=r"(r[3]) : "r"(addr));
}
__device__ __forceinline__ void mma16816(float* c, const unsigned int* a,
                                         unsigned int b0, unsigned int b1) {
    asm volatile(
        "mma.sync.aligned.m16n8k16.row.col.f32.f16.f16.f32 "
        "{%0,%1,%2,%3}, {%4,%5,%6,%7}, {%8,%9}, {%0,%1,%2,%3};"
        : "+f"(c[0]), "+f"(c[1]), "+f"(c[2]), "+f"(c[3])
        : "r"(a[0]), "r"(a[1]), "r"(a[2]), "r"(a[3]), "r"(b0), "r"(b1));
}
__device__ __forceinline__ uint4 cvt8h(float4 v0, float4 v1) {
    __half2 h0 = __floats2half2_rn(v0.x, v0.y);
    __half2 h1 = __floats2half2_rn(v0.z, v0.w);
    __half2 h2 = __floats2half2_rn(v1.x, v1.y);
    __half2 h3 = __floats2half2_rn(v1.z, v1.w);
    return make_uint4(*(unsigned int*)&h0, *(unsigned int*)&h1,
                      *(unsigned int*)&h2, *(unsigned int*)&h3);
}

// ---------------- W pre-conversion (unchanged, R12-proven) ----------------
__global__ void wcvt_kernel(const float* __restrict__ W, int H) {
    const int idx = blockIdx.x * 256 + threadIdx.x;
    const int nchunks = (H / 32) * 512;
    if (idx >= nchunks) return;
    const int t = idx >> 9;
    const int rc = idx & 511;
    const int r = rc >> 2;
    const int p = rc & 3;
    const int c = p ^ ((r >> 1) & 3);
    const float4* src = (const float4*)(W + (size_t)r * H + t * 32 + c * 8);
    *(uint4*)(g_wfp16 + (size_t)idx * 16) = cvt8h(src[0], src[1]);
}

__global__ __launch_bounds__(NTHREADS, 1)
void gemm_kernel(const float* __restrict__ X,
                 const float* __restrict__ bias,
                 float* __restrict__ out_vals,
                 float* __restrict__ out_idx,
                 float* __restrict__ out_logits,
                 int T, int H)
{
    const int tid  = threadIdx.x;
    const int wid  = tid >> 5;
    const int lane = tid & 31;
    const int rowBase = blockIdx.x * BM;
    const unsigned int sb = smem_u32(smem);

    const int m_base = (wid >> 2) * 32;
    const int n_base = (wid & 3) * 32;

    if (tid < BN) ((float*)(smem + SM_BIAS))[tid] = bias[tid];

    const int nst = H / 32;   // 90

    // ---- X LDG + STS mapping: row = tid>>2, lq = tid&3 (8 f32/thread) ----
    const int lrow = tid >> 2;
    const int lq   = tid & 3;
    const float* xsrc = X + (size_t)(rowBase + lrow) * H + lq * 8;
    const unsigned int fst = (unsigned int)(lrow * 64) +
                             ((unsigned int)(lq ^ ((lrow >> 1) & 3)) << 4);

    // ---- B cp.async mapping: 8192B/stage = 512 x 16B chunks -> 1/thread ----
    const unsigned int bdst = sb + SM_TILES + TILE_A + (unsigned int)tid * 16;
    const unsigned char* bsrc = g_wfp16 + (size_t)tid * 16;

    // ---- ldmatrix per-lane pieces ----
    const int arow0 = m_base + ((lane >> 3) & 1) * 8 + (lane & 7);
    const int brow0 = n_base + (lane >> 4) * 8 + (lane & 7);
    const unsigned int acol = (unsigned int)(lane >> 4);
    const unsigned int bcol = (unsigned int)((lane >> 3) & 1);

    unsigned int aoff[2], axor[2], boff[2], bxor[2];
    #pragma unroll
    for (int mt = 0; mt < 2; mt++) {
        const int r = arow0 + mt * 16;
        aoff[mt] = (unsigned int)(r * 64);
        axor[mt] = (unsigned int)((r >> 1) & 3);
    }
    #pragma unroll
    for (int nt = 0; nt < 2; nt++) {
        const int r = brow0 + nt * 16;
        boff[nt] = (unsigned int)(r * 64);
        bxor[nt] = (unsigned int)((r >> 1) & 3);
    }

    const unsigned int ftiles = sb + SM_TILES;

    float acc[2][4][4];
    #pragma unroll
    for (int mt = 0; mt < 2; mt++)
        #pragma unroll
        for (int n8 = 0; n8 < 4; n8++)
            #pragma unroll
            for (int i = 0; i < 4; i++) acc[mt][n8][i] = 0.0f;

    // ---- prologue: B0->g0, B1->g1; X0 LDG+STS; X1 LDG ----
    cp16(bdst, bsrc);
    asm volatile("cp.async.commit_group;");
    cp16(bdst + FBUF_B, bsrc + 8192);
    asm volatile("cp.async.commit_group;");

    float4 xv0 = *(const float4*)(xsrc);
    float4 xv1 = *(const float4*)(xsrc + 4);
    *(uint4*)(smem + SM_TILES + fst) = cvt8h(xv0, xv1);       // STS X0 -> fbuf0
    xv0 = *(const float4*)(xsrc + 32);                        // LDG X1
    xv1 = *(const float4*)(xsrc + 36);

    for (int t = 0; t < nst; t++) {
        // STS X(t+1) from regs into fbuf[(t+1)&3] (readers were MMA(t-3))
        if (t + 1 < nst) {
            char* fb = smem + SM_TILES + ((t + 1) & 3) * FBUF_B;
            *(uint4*)(fb + fst) = cvt8h(xv0, xv1);
        }
        if (t + 2 < nst) {
            // issue B(t+2); LDG X(t+2); then wait for B(t)
            cp16(bdst + (unsigned int)(((t + 2) & 3) * FBUF_B),
                 bsrc + (size_t)(t + 2) * 8192);
            asm volatile("cp.async.commit_group;");
            xv0 = *(const float4*)(xsrc + (t + 2) * 32);
            xv1 = *(const float4*)(xsrc + (t + 2) * 32 + 4);
            asm volatile("cp.async.wait_group 2;");
        } else if (t + 2 == nst) {
            asm volatile("cp.async.wait_group 1;");
        } else {
            asm volatile("cp.async.wait_group 0;");
        }
        __syncthreads();   // X(t) STS (prev iter) + B(t) visible

        // ---- MMA(t) on fbuf[t&3] ----
        const unsigned int base = ftiles + (unsigned int)(t & 3) * FBUF_B;
        #pragma unroll
        for (int kk = 0; kk < 2; kk++) {
            unsigned int ah[2][4], bh[2][4];
            #pragma unroll
            for (int mt = 0; mt < 2; mt++) {
                const unsigned int c = (unsigned int)(kk * 2) + acol;
                ldm4(ah[mt], base + aoff[mt] + ((c ^ axor[mt]) << 4));
            }
            #pragma unroll
            for (int nt = 0; nt < 2; nt++) {
                const unsigned int c = (unsigned int)(kk * 2) + bcol;
                ldm4(bh[nt], base + TILE_A + boff[nt] + ((c ^ bxor[nt]) << 4));
            }
            #pragma unroll
            for (int mt = 0; mt < 2; mt++)
                #pragma unroll
                for (int nt = 0; nt < 2; nt++)
                    #pragma unroll
                    for (int p = 0; p < 2; p++)
                        mma16816(acc[mt][nt * 2 + p], ah[mt],
                                 bh[nt][p * 2], bh[nt][p * 2 + 1]);
        }
    }
    __syncthreads();   // fbuf dead; reuse as logits staging

    // ---------------- Epilogue ----------------
    float* Ls = (float*)(smem + SM_TILES);            // [128][LPAD]
    const float* bsm = (const float*)(smem + SM_BIAS);

    #pragma unroll
    for (int mt = 0; mt < 2; mt++) {
        const int r1 = m_base + mt * 16 + (lane >> 2);
        #pragma unroll
        for (int n8 = 0; n8 < 4; n8++) {
            const int c = n_base + n8 * 8 + (lane & 3) * 2;
            const float b0 = bsm[c], b1 = bsm[c + 1];
            Ls[r1 * LPAD + c]           = acc[mt][n8][0] + b0;
            Ls[r1 * LPAD + c + 1]       = acc[mt][n8][1] + b1;
            Ls[(r1 + 8) * LPAD + c]     = acc[mt][n8][2] + b0;
            Ls[(r1 + 8) * LPAD + c + 1] = acc[mt][n8][3] + b1;
        }
    }
    __syncthreads();

    // logits to gmem: 4096 float4
    #pragma unroll
    for (int i = 0; i < 8; i++) {
        const int idx = tid + NTHREADS * i;
        const int row = idx >> 5;
        const int c4  = idx & 31;
        float4 v;
        v.x = Ls[row * LPAD + c4 * 4 + 0];
        v.y = Ls[row * LPAD + c4 * 4 + 1];
        v.z = Ls[row * LPAD + c4 * 4 + 2];
        v.w = Ls[row * LPAD + c4 * 4 + 3];
        *(float4*)&out_logits[(size_t)(rowBase + row) * BN + c4 * 4] = v;
    }

    // top-8 scan + provisional outputs + candidate records
    if (tid < BM) {
        const int token = rowBase + tid;
        const float* row = &Ls[tid * LPAD];
        float tv[8];
        int   ti[8];
        #pragma unroll
        for (int s = 0; s < 8; s++) { tv[s] = -1e30f; ti[s] = 0; }
        for (int e = 0; e < BN; e++) {
            float val = row[e];
            if (val > tv[7]) {
                tv[7] = val; ti[7] = e;
                #pragma unroll
                for (int s = 7; s > 0; s--) {
                    if (tv[s] > tv[s - 1]) {     // strict >: earlier index wins
                        float fv = tv[s]; tv[s] = tv[s-1]; tv[s-1] = fv;
                        int   fi = ti[s]; ti[s] = ti[s-1]; ti[s-1] = fi;
                    }
                }
            }
        }
        bool ambig = (tv[0] - tv[1] < AMBIG_EPS) |
                     (tv[1] - tv[2] < AMBIG_EPS) |
                     (tv[2] - tv[3] < AMBIG_EPS) |
                     (tv[3] - tv[4] < AMBIG_EPS);
        if (ambig) {
            const int mode = (tv[3] - tv[7] < AMBIG_EPS) ? 1 : 0;
            const int lo = ti[0] | (ti[1] << 8) | (ti[2] << 16) | (ti[3] << 24);
            const int hi = ti[4] | (ti[5] << 8) | (ti[6] << 16) | (ti[7] << 24);
            int p = atomicAdd(&g_count, 1);
            g_rec[p] = make_int4(token, lo, hi, mode);
        }
        const float mx = tv[0];
        float e0 = expf(tv[0] - mx);
        float e1 = expf(tv[1] - mx);
        float e2 = expf(tv[2] - mx);
        float e3 = expf(tv[3] - mx);
        const float inv = 1.0f / (e0 + e1 + e2 + e3);
        out_vals[(size_t)token * 4 + 0] = e0 * inv;
        out_vals[(size_t)token * 4 + 1] = e1 * inv;
        out_vals[(size_t)token * 4 + 2] = e2 * inv;
        out_vals[(size_t)token * 4 + 3] = e3 * inv;
        out_idx[(size_t)token * 4 + 0] = (float)ti[0];
        out_idx[(size_t)token * 4 + 1] = (float)ti[1];
        out_idx[(size_t)token * 4 + 2] = (float)ti[2];
        out_idx[(size_t)token * 4 + 3] = (float)ti[3];
    }
}

// ---------------- Candidate refinement (grid 2048; 2 interleaved chains) ----------------
__global__ __launch_bounds__(256)
void refine_kernel(const float* __restrict__ X,
                   const float* __restrict__ W,
                   const float* __restrict__ bias,
                   float* __restrict__ out_vals,
                   float* __restrict__ out_idx,
                   int T, int H)
{
    const int cnt = *(volatile int*)&g_count;
    __shared__ double s_partial[256];
    __shared__ double s_logit[128];
    __shared__ double s_l8[8];
    __shared__ int    s_i8[8];

    const int tid  = threadIdx.x;
    const int wid  = tid >> 5;
    const int lane = tid & 31;

    for (int it = blockIdx.x; it < cnt; it += gridDim.x) {
        const int4 rec = g_rec[it];
        const int token = rec.x;

        if (rec.w == 0) {
            const int packed = (wid < 4) ? rec.y : rec.z;
            const int eidx = (packed >> ((wid & 3) * 8)) & 0xFF;

            const float* xr = X + (size_t)token * H;
            const float* wr = W + (size_t)eidx * H;

            // two interleaved compensated chains (halves dependent latency)
            float s0 = 0.f, c0 = 0.f, s1 = 0.f, c1 = 0.f;
            const int n64 = H >> 6;             // 45
            for (int i = 0; i < n64; i++) {
                const int k = i * 64 + lane;
                {
                    float a = xr[k], b = wr[k];
                    float p  = a * b;
                    float pe = fmaf(a, b, -p);
                    float t2 = s0 + p;
                    float z  = t2 - s0;
                    float er = (s0 - (t2 - z)) + (p - z);
                    s0 = t2;
                    c0 += er + pe;
                }
                {
                    float a = xr[k + 32], b = wr[k + 32];
                    float p  = a * b;
                    float pe = fmaf(a, b, -p);
                    float t2 = s1 + p;
                    float z  = t2 - s1;
                    float er = (s1 - (t2 - z)) + (p - z);
                    s1 = t2;
                    c1 += er + pe;
                }
            }
            double part = ((double)s0 + (double)c0) + ((double)s1 + (double)c1);
            #pragma unroll
            for (int off = 16; off > 0; off >>= 1)
                part += __shfl_xor_sync(0xFFFFFFFFu, part, off);
            if (lane == 0) {
                s_l8[wid] = part + (double)bias[eidx];
                s_i8[wid] = eidx;
            }
            __syncthreads();

            if (tid == 0) {
                double v[8]; int ix[8];
                #pragma unroll
                for (int j = 0; j < 8; j++) { v[j] = s_l8[j]; ix[j] = s_i8[j]; }
                #pragma unroll
                for (int a2 = 0; a2 < 4; a2++) {
                    int best = a2;
                    #pragma unroll
                    for (int b2 = a2 + 1; b2 < 8; b2++) {
                        if (v[b2] > v[best] ||
                            (v[b2] == v[best] && ix[b2] < ix[best])) best = b2;
                    }
                    double fv = v[a2]; v[a2] = v[best]; v[best] = fv;
                    int    fi = ix[a2]; ix[a2] = ix[best]; ix[best] = fi;
                }
                float v0 = (float)v[0], v1 = (float)v[1],
                      v2 = (float)v[2], v3 = (float)v[3];
                float e0 = expf(v0 - v0);
                float e1 = expf(v1 - v0);
                float e2 = expf(v2 - v0);
                float e3 = expf(v3 - v0);
                float inv = 1.0f / (e0 + e1 + e2 + e3);
                out_vals[(size_t)token * 4 + 0] = e0 * inv;
                out_vals[(size_t)token * 4 + 1] = e1 * inv;
                out_vals[(size_t)token * 4 + 2] = e2 * inv;
                out_vals[(size_t)token * 4 + 3] = e3 * inv;
                out_idx[(size_t)token * 4 + 0] = (float)ix[0];
                out_idx[(size_t)token * 4 + 1] = (float)ix[1];
                out_idx[(size_t)token * 4 + 2] = (float)ix[2];
                out_idx[(size_t)token * 4 + 3] = (float)ix[3];
            }
            __syncthreads();
        } else {
            const int e = tid >> 1;
            const int h = tid & 1;
            const int half = H >> 1;
            const int nq = half >> 2;
            const float4* xr = (const float4*)(X + (size_t)token * H + (size_t)h * half);
            const float4* wr = (const float4*)(W + (size_t)e * H + (size_t)h * half);

            float s[4] = {0.f, 0.f, 0.f, 0.f};
            float c[4] = {0.f, 0.f, 0.f, 0.f};
            for (int i = 0; i < nq; i++) {
                float4 xvv = xr[i];
                float4 wvv = wr[i];
                float a4[4] = {xvv.x, xvv.y, xvv.z, xvv.w};
                float b4[4] = {wvv.x, wvv.y, wvv.z, wvv.w};
                #pragma unroll
                for (int l = 0; l < 4; l++) {
                    float p  = a4[l] * b4[l];
                    float pe = fmaf(a4[l], b4[l], -p);
                    float t2 = s[l] + p;
                    float z  = t2 - s[l];
                    float er = (s[l] - (t2 - z)) + (p - z);
                    s[l] = t2;
                    c[l] += er + pe;
                }
            }
            double tot = 0.0;
            #pragma unroll
            for (int l = 0; l < 4; l++) tot += (double)s[l] + (double)c[l];
            s_partial[tid] = tot;
            __syncthreads();

            if (h == 0)
                s_logit[e] = s_partial[2 * e] + s_partial[2 * e + 1] + (double)bias[e];
            __syncthreads();

            if (tid == 0) {
                double tv[4] = {-1e300, -1e300, -1e300, -1e300};
                int    ti[4] = {0, 0, 0, 0};
                for (int k = 0; k < 128; k++) {
                    double val = s_logit[k];
                    if (val > tv[3]) {
                        tv[3] = val; ti[3] = k;
                        #pragma unroll
                        for (int s2 = 3; s2 > 0; s2--) {
                            if (tv[s2] > tv[s2 - 1]) {
                                double fv = tv[s2]; tv[s2] = tv[s2-1]; tv[s2-1] = fv;
                                int    fi = ti[s2]; ti[s2] = ti[s2-1]; ti[s2-1] = fi;
                            }
                        }
                    }
                }
                float v0 = (float)tv[0], v1 = (float)tv[1],
                      v2 = (float)tv[2], v3 = (float)tv[3];
                float e0 = expf(v0 - v0);
                float e1 = expf(v1 - v0);
                float e2 = expf(v2 - v0);
                float e3 = expf(v3 - v0);
                float inv = 1.0f / (e0 + e1 + e2 + e3);
                out_vals[(size_t)token * 4 + 0] = e0 * inv;
                out_vals[(size_t)token * 4 + 1] = e1 * inv;
                out_vals[(size_t)token * 4 + 2] = e2 * inv;
                out_vals[(size_t)token * 4 + 3] = e3 * inv;
                out_idx[(size_t)token * 4 + 0] = (float)ti[0];
                out_idx[(size_t)token * 4 + 1] = (float)ti[1];
                out_idx[(size_t)token * 4 + 2] = (float)ti[2];
                out_idx[(size_t)token * 4 + 3] = (float)ti[3];
            }
            __syncthreads();
        }
    }

    // last finishing block resets the worklist for the next graph replay
    __syncthreads();
    if (threadIdx.x == 0) {
        const int d = atomicAdd(&g_done, 1);
        if (d == (int)gridDim.x - 1) {
            g_count = 0;
            g_done  = 0;
        }
    }
}

extern "C" void kernel_launch(void* const* d_in, const int* in_sizes, int n_in,
                              void* d_out, int out_size)
{
    const float* X    = (const float*)d_in[0];
    const float* W    = (const float*)d_in[1];
    const float* bias = (const float*)d_in[2];

    const int E = in_sizes[2];          // 128
    const int H = in_sizes[1] / E;      // 2880
    const int T = in_sizes[0] / H;      // 16384

    float* out        = (float*)d_out;
    float* out_vals   = out;
    float* out_idx    = out + (size_t)T * 4;
    float* out_logits = out + (size_t)T * 8;

    cudaFuncSetAttribute(gemm_kernel,
                         cudaFuncAttributeMaxDynamicSharedMemorySize,
                         SMEM_TOTAL);

    const int nchunks = (H / 32) * 512;            // 46080
    wcvt_kernel<<<(nchunks + 255) / 256, 256>>>(W, H);
    gemm_kernel<<<T / BM, NTHREADS, SMEM_TOTAL>>>(
        X, bias, out_vals, out_idx, out_logits, T, H);
    refine_kernel<<<2048, 256>>>(X, W, bias, out_vals, out_idx, T, H);
}

// round 15
// speedup vs baseline: 1.1217x; 1.1095x over previous
#include <cuda_runtime.h>
#include <cuda_fp16.h>
#include <math.h>

// X [T=16384, H=2880] f32; W [E=128, H=2880] f32; bias [E=128] f32
// d_out f32: [0,T*4) softmax vals | [T*4,T*8) indices | [T*8,..) logits [T,E]
//
// Kernel A (wcvt): W f32 -> fp16, pre-swizzled tile layout (R12-proven).
// Kernel B (gemm): R12-proven 1-pass fp16 mma.sync GEMM, VERBATIM:
//   X cp.async f32 -> 4-deep ring + in-kernel cvt; B cp.async fp16 direct.
//   Epilogue: bias, logits, top-8, candidate records (EPS=2.5e-3).
// Kernel C (refine): candidate refinement, grid 2048; ONLY change vs R12:
//   mode-0 dot uses two interleaved compensated chains (ILP-2, still exact).

#define NTHREADS 512
#define BM 128
#define BN 128
#define LPAD 129
#define AMBIG_EPS 2.5e-3f

#define SM_BIAS   128
#define SM_XSTG   1024
#define XSLOT_B   (128 * 144)                 // f32 stage: 128 rows x 144B
#define SM_TILES  (SM_XSTG + 4 * XSLOT_B)     // 74752
#define TILE_B    8192                        // fp16 tile: 128 rows x 64B
#define FBUF_B    (2 * TILE_B)                // A + B
#define SMEM_TOTAL (SM_TILES + 4 * FBUF_B)    // 140288

__device__ int  g_count;
__device__ int  g_done;
__device__ int4 g_rec[16384];                         // {token, idx0..3, idx4..7, mode}
__device__ __align__(16) unsigned char g_wfp16[90 * 8192];  // 737,280 B

extern __shared__ __align__(1024) char smem[];

__device__ __forceinline__ unsigned int smem_u32(const void* p) {
    unsigned int a;
    asm("{ .reg .u64 t; cvta.to.shared.u64 t, %1; cvt.u32.u64 %0, t; }"
        : "=r"(a) : "l"(p));
    return a;
}
__device__ __forceinline__ void cp16(unsigned int dst, const void* src) {
    asm volatile("cp.async.cg.shared.global [%0], [%1], 16;"
                 :: "r"(dst), "l"(src));
}
__device__ __forceinline__ void ldm4(unsigned int* r, unsigned int addr) {
    asm volatile("ldmatrix.sync.aligned.m8n8.x4.shared.b16 {%0,%1,%2,%3}, [%4];"
                 : "=r"(r[0]), "=r"(r[1]), "=r"(r[2]), "=r"(r[3]) : "r"(addr));
}
__device__ __forceinline__ void mma16816(float* c, const unsigned int* a,
                                         unsigned int b0, unsigned int b1) {
    asm volatile(
        "mma.sync.aligned.m16n8k16.row.col.f32.f16.f16.f32 "
        "{%0,%1,%2,%3}, {%4,%5,%6,%7}, {%8,%9}, {%0,%1,%2,%3};"
        : "+f"(c[0]), "+f"(c[1]), "+f"(c[2]), "+f"(c[3])
        : "r"(a[0]), "r"(a[1]), "r"(a[2]), "r"(a[3]), "r"(b0), "r"(b1));
}
__device__ __forceinline__ uint4 cvt8h(float4 v0, float4 v1) {
    __half2 h0 = __floats2half2_rn(v0.x, v0.y);
    __half2 h1 = __floats2half2_rn(v0.z, v0.w);
    __half2 h2 = __floats2half2_rn(v1.x, v1.y);
    __half2 h3 = __floats2half2_rn(v1.z, v1.w);
    return make_uint4(*(unsigned int*)&h0, *(unsigned int*)&h1,
                      *(unsigned int*)&h2, *(unsigned int*)&h3);
}

// ---------------- W pre-conversion (R12-proven) ----------------
__global__ void wcvt_kernel(const float* __restrict__ W, int H) {
    const int idx = blockIdx.x * 256 + threadIdx.x;
    const int nchunks = (H / 32) * 512;
    if (idx >= nchunks) return;
    const int t = idx >> 9;
    const int rc = idx & 511;
    const int r = rc >> 2;
    const int p = rc & 3;
    const int c = p ^ ((r >> 1) & 3);
    const float4* src = (const float4*)(W + (size_t)r * H + t * 32 + c * 8);
    *(uint4*)(g_wfp16 + (size_t)idx * 16) = cvt8h(src[0], src[1]);
}

__global__ __launch_bounds__(NTHREADS, 1)
void gemm_kernel(const float* __restrict__ X,
                 const float* __restrict__ bias,
                 float* __restrict__ out_vals,
                 float* __restrict__ out_idx,
                 float* __restrict__ out_logits,
                 int T, int H)
{
    const int tid  = threadIdx.x;
    const int wid  = tid >> 5;
    const int lane = tid & 31;
    const int rowBase = blockIdx.x * BM;
    const unsigned int sb = smem_u32(smem);

    const int m_base = (wid >> 2) * 32;
    const int n_base = (wid & 3) * 32;

    if (tid < BN) ((float*)(smem + SM_BIAS))[tid] = bias[tid];

    const int nst = H / 32;   // 90

    // ---- X cp.async mapping ----
    const int xr0 = tid >> 3;
    const int xc  = tid & 7;
    const float* xsrc0 = X + (size_t)(rowBase + xr0) * H + xc * 4;
    const float* xsrc1 = X + (size_t)(rowBase + xr0 + 64) * H + xc * 4;
    const unsigned int xd0 = sb + SM_XSTG + (unsigned int)(xr0 * 144 + xc * 16);
    const unsigned int xd1 = xd0 + 64 * 144;

    // ---- X cvt mapping ----
    const int lrow = tid >> 2;
    const int lq   = tid & 3;
    const unsigned int xstg_rd = (unsigned int)(lrow * 144 + lq * 32);
    const unsigned int fst = (unsigned int)(lrow * 64) +
                             ((unsigned int)(lq ^ ((lrow >> 1) & 3)) << 4);

    // ---- B cp.async mapping: flat 16B chunk per thread ----
    const unsigned int bdst = sb + SM_TILES + TILE_B + (unsigned int)tid * 16;
    const unsigned char* bsrc = g_wfp16 + (size_t)tid * 16;

    // ---- ldmatrix per-lane pieces ----
    const int arow0 = m_base + ((lane >> 3) & 1) * 8 + (lane & 7);
    const int brow0 = n_base + (lane >> 4) * 8 + (lane & 7);
    const unsigned int acol = (unsigned int)(lane >> 4);
    const unsigned int bcol = (unsigned int)((lane >> 3) & 1);

    unsigned int aoff[2], axor[2], boff[2], bxor[2];
    #pragma unroll
    for (int mt = 0; mt < 2; mt++) {
        const int r = arow0 + mt * 16;
        aoff[mt] = (unsigned int)(r * 64);
        axor[mt] = (unsigned int)((r >> 1) & 3);
    }
    #pragma unroll
    for (int nt = 0; nt < 2; nt++) {
        const int r = brow0 + nt * 16;
        boff[nt] = (unsigned int)(r * 64);
        bxor[nt] = (unsigned int)((r >> 1) & 3);
    }

    const unsigned int ftiles = sb + SM_TILES;

    float acc[2][4][4];
    #pragma unroll
    for (int mt = 0; mt < 2; mt++)
        #pragma unroll
        for (int n8 = 0; n8 < 4; n8++)
            #pragma unroll
            for (int i = 0; i < 4; i++) acc[mt][n8][i] = 0.0f;

    // ---- prologue: G0={X0,B0} G1={X1,B1} G2={X2} G3={X3} ----
    #pragma unroll
    for (int s = 0; s < 4; s++) {
        const unsigned int so = (unsigned int)(s * XSLOT_B);
        cp16(xd0 + so, xsrc0 + s * 32);
        cp16(xd1 + so, xsrc1 + s * 32);
        if (s < 2)
            cp16(bdst + (unsigned int)(s * FBUF_B), bsrc + (size_t)s * 8192);
        asm volatile("cp.async.commit_group;");
    }

    asm volatile("cp.async.wait_group 3;");
    __syncthreads();
    {   // cvt X0 -> fbuf0 A
        const char* xs = smem + SM_XSTG;
        float4 x0 = *(const float4*)(xs + xstg_rd);
        float4 x1 = *(const float4*)(xs + xstg_rd + 16);
        *(uint4*)(smem + SM_TILES + fst) = cvt8h(x0, x1);
    }
    asm volatile("cp.async.wait_group 2;");
    __syncthreads();
    {   // cvt X1 -> fbuf1 A
        const char* xs = smem + SM_XSTG + XSLOT_B;
        float4 x0 = *(const float4*)(xs + xstg_rd);
        float4 x1 = *(const float4*)(xs + xstg_rd + 16);
        *(uint4*)(smem + SM_TILES + FBUF_B + fst) = cvt8h(x0, x1);
    }
    __syncthreads();

    for (int t = 0; t < nst; t++) {
        if (t + 2 < nst) {
            cp16(bdst + (unsigned int)(((t + 2) & 3) * FBUF_B),
                 bsrc + (size_t)(t + 2) * 8192);
            if (t + 4 < nst) {
                const unsigned int so = (unsigned int)(((t + 4) & 3) * XSLOT_B);
                cp16(xd0 + so, xsrc0 + (t + 4) * 32);
                cp16(xd1 + so, xsrc1 + (t + 4) * 32);
            }
            asm volatile("cp.async.commit_group;");
            asm volatile("cp.async.wait_group 2;");
            __syncthreads();   // X(t+2), B(t) visible; fbuf[(t+2)&3] A free

            const char* xs = smem + SM_XSTG + ((t + 2) & 3) * XSLOT_B;
            float4 x0 = *(const float4*)(xs + xstg_rd);
            float4 x1 = *(const float4*)(xs + xstg_rd + 16);
            char* fb = smem + SM_TILES + ((t + 2) & 3) * FBUF_B;
            *(uint4*)(fb + fst) = cvt8h(x0, x1);
        } else if (t + 2 == nst) {
            asm volatile("cp.async.wait_group 1;");
            __syncthreads();
        } else {
            asm volatile("cp.async.wait_group 0;");
            __syncthreads();
        }

        // ---- MMA(t) on fbuf[t&3] ----
        const unsigned int base = ftiles + (unsigned int)(t & 3) * FBUF_B;
        #pragma unroll
        for (int kk = 0; kk < 2; kk++) {
            unsigned int ah[2][4], bh[2][4];
            #pragma unroll
            for (int mt = 0; mt < 2; mt++) {
                const unsigned int c = (unsigned int)(kk * 2) + acol;
                ldm4(ah[mt], base + aoff[mt] + ((c ^ axor[mt]) << 4));
            }
            #pragma unroll
            for (int nt = 0; nt < 2; nt++) {
                const unsigned int c = (unsigned int)(kk * 2) + bcol;
                ldm4(bh[nt], base + TILE_B + boff[nt] + ((c ^ bxor[nt]) << 4));
            }
            #pragma unroll
            for (int mt = 0; mt < 2; mt++)
                #pragma unroll
                for (int nt = 0; nt < 2; nt++)
                    #pragma unroll
                    for (int p = 0; p < 2; p++)
                        mma16816(acc[mt][nt * 2 + p], ah[mt],
                                 bh[nt][p * 2], bh[nt][p * 2 + 1]);
        }
    }
    __syncthreads();   // rings free; reuse as logits staging

    // ---------------- Epilogue ----------------
    float* Ls = (float*)(smem + SM_XSTG);             // [128][LPAD]
    const float* bsm = (const float*)(smem + SM_BIAS);

    #pragma unroll
    for (int mt = 0; mt < 2; mt++) {
        const int r1 = m_base + mt * 16 + (lane >> 2);
        #pragma unroll
        for (int n8 = 0; n8 < 4; n8++) {
            const int c = n_base + n8 * 8 + (lane & 3) * 2;
            const float b0 = bsm[c], b1 = bsm[c + 1];
            Ls[r1 * LPAD + c]           = acc[mt][n8][0] + b0;
            Ls[r1 * LPAD + c + 1]       = acc[mt][n8][1] + b1;
            Ls[(r1 + 8) * LPAD + c]     = acc[mt][n8][2] + b0;
            Ls[(r1 + 8) * LPAD + c + 1] = acc[mt][n8][3] + b1;
        }
    }
    __syncthreads();

    // logits to gmem: 4096 float4
    #pragma unroll
    for (int i = 0; i < 8; i++) {
        const int idx = tid + NTHREADS * i;
        const int row = idx >> 5;
        const int c4  = idx & 31;
        float4 v;
        v.x = Ls[row * LPAD + c4 * 4 + 0];
        v.y = Ls[row * LPAD + c4 * 4 + 1];
        v.z = Ls[row * LPAD + c4 * 4 + 2];
        v.w = Ls[row * LPAD + c4 * 4 + 3];
        *(float4*)&out_logits[(size_t)(rowBase + row) * BN + c4 * 4] = v;
    }

    // top-8 scan + provisional outputs + candidate records
    if (tid < BM) {
        const int token = rowBase + tid;
        const float* row = &Ls[tid * LPAD];
        float tv[8];
        int   ti[8];
        #pragma unroll
        for (int s = 0; s < 8; s++) { tv[s] = -1e30f; ti[s] = 0; }
        for (int e = 0; e < BN; e++) {
            float val = row[e];
            if (val > tv[7]) {
                tv[7] = val; ti[7] = e;
                #pragma unroll
                for (int s = 7; s > 0; s--) {
                    if (tv[s] > tv[s - 1]) {     // strict >: earlier index wins
                        float fv = tv[s]; tv[s] = tv[s-1]; tv[s-1] = fv;
                        int   fi = ti[s]; ti[s] = ti[s-1]; ti[s-1] = fi;
                    }
                }
            }
        }
        bool ambig = (tv[0] - tv[1] < AMBIG_EPS) |
                     (tv[1] - tv[2] < AMBIG_EPS) |
                     (tv[2] - tv[3] < AMBIG_EPS) |
                     (tv[3] - tv[4] < AMBIG_EPS);
        if (ambig) {
            const int mode = (tv[3] - tv[7] < AMBIG_EPS) ? 1 : 0;
            const int lo = ti[0] | (ti[1] << 8) | (ti[2] << 16) | (ti[3] << 24);
            const int hi = ti[4] | (ti[5] << 8) | (ti[6] << 16) | (ti[7] << 24);
            int p = atomicAdd(&g_count, 1);
            g_rec[p] = make_int4(token, lo, hi, mode);
        }
        const float mx = tv[0];
        float e0 = expf(tv[0] - mx);
        float e1 = expf(tv[1] - mx);
        float e2 = expf(tv[2] - mx);
        float e3 = expf(tv[3] - mx);
        const float inv = 1.0f / (e0 + e1 + e2 + e3);
        out_vals[(size_t)token * 4 + 0] = e0 * inv;
        out_vals[(size_t)token * 4 + 1] = e1 * inv;
        out_vals[(size_t)token * 4 + 2] = e2 * inv;
        out_vals[(size_t)token * 4 + 3] = e3 * inv;
        out_idx[(size_t)token * 4 + 0] = (float)ti[0];
        out_idx[(size_t)token * 4 + 1] = (float)ti[1];
        out_idx[(size_t)token * 4 + 2] = (float)ti[2];
        out_idx[(size_t)token * 4 + 3] = (float)ti[3];
    }
}

// ---------------- Candidate refinement (grid 2048; ILP-2 exact chains) ----------------
__global__ __launch_bounds__(256)
void refine_kernel(const float* __restrict__ X,
                   const float* __restrict__ W,
                   const float* __restrict__ bias,
                   float* __restrict__ out_vals,
                   float* __restrict__ out_idx,
                   int T, int H)
{
    const int cnt = *(volatile int*)&g_count;
    __shared__ double s_partial[256];
    __shared__ double s_logit[128];
    __shared__ double s_l8[8];
    __shared__ int    s_i8[8];

    const int tid  = threadIdx.x;
    const int wid  = tid >> 5;
    const int lane = tid & 31;

    for (int it = blockIdx.x; it < cnt; it += gridDim.x) {
        const int4 rec = g_rec[it];
        const int token = rec.x;

        if (rec.w == 0) {
            const int packed = (wid < 4) ? rec.y : rec.z;
            const int eidx = (packed >> ((wid & 3) * 8)) & 0xFF;

            const float* xr = X + (size_t)token * H;
            const float* wr = W + (size_t)eidx * H;

            // two interleaved compensated chains (ILP-2, still exact)
            float s0 = 0.f, c0 = 0.f, s1 = 0.f, c1 = 0.f;
            const int n64 = H >> 6;             // 45
            for (int i = 0; i < n64; i++) {
                const int k = i * 64 + lane;
                {
                    float a = xr[k], b = wr[k];
                    float p  = a * b;
                    float pe = fmaf(a, b, -p);
                    float t2 = s0 + p;
                    float z  = t2 - s0;
                    float er = (s0 - (t2 - z)) + (p - z);
                    s0 = t2;
                    c0 += er + pe;
                }
                {
                    float a = xr[k + 32], b = wr[k + 32];
                    float p  = a * b;
                    float pe = fmaf(a, b, -p);
                    float t2 = s1 + p;
                    float z  = t2 - s1;
                    float er = (s1 - (t2 - z)) + (p - z);
                    s1 = t2;
                    c1 += er + pe;
                }
            }
            double part = ((double)s0 + (double)c0) + ((double)s1 + (double)c1);
            #pragma unroll
            for (int off = 16; off > 0; off >>= 1)
                part += __shfl_xor_sync(0xFFFFFFFFu, part, off);
            if (lane == 0) {
                s_l8[wid] = part + (double)bias[eidx];
                s_i8[wid] = eidx;
            }
            __syncthreads();

            if (tid == 0) {
                double v[8]; int ix[8];
                #pragma unroll
                for (int j = 0; j < 8; j++) { v[j] = s_l8[j]; ix[j] = s_i8[j]; }
                #pragma unroll
                for (int a2 = 0; a2 < 4; a2++) {
                    int best = a2;
                    #pragma unroll
                    for (int b2 = a2 + 1; b2 < 8; b2++) {
                        if (v[b2] > v[best] ||
                            (v[b2] == v[best] && ix[b2] < ix[best])) best = b2;
                    }
                    double fv = v[a2]; v[a2] = v[best]; v[best] = fv;
                    int    fi = ix[a2]; ix[a2] = ix[best]; ix[best] = fi;
                }
                float v0 = (float)v[0], v1 = (float)v[1],
                      v2 = (float)v[2], v3 = (float)v[3];
                float e0 = expf(v0 - v0);
                float e1 = expf(v1 - v0);
                float e2 = expf(v2 - v0);
                float e3 = expf(v3 - v0);
                float inv = 1.0f / (e0 + e1 + e2 + e3);
                out_vals[(size_t)token * 4 + 0] = e0 * inv;
                out_vals[(size_t)token * 4 + 1] = e1 * inv;
                out_vals[(size_t)token * 4 + 2] = e2 * inv;
                out_vals[(size_t)token * 4 + 3] = e3 * inv;
                out_idx[(size_t)token * 4 + 0] = (float)ix[0];
                out_idx[(size_t)token * 4 + 1] = (float)ix[1];
                out_idx[(size_t)token * 4 + 2] = (float)ix[2];
                out_idx[(size_t)token * 4 + 3] = (float)ix[3];
            }
            __syncthreads();
        } else {
            const int e = tid >> 1;
            const int h = tid & 1;
            const int half = H >> 1;
            const int nq = half >> 2;
            const float4* xr = (const float4*)(X + (size_t)token * H + (size_t)h * half);
            const float4* wr = (const float4*)(W + (size_t)e * H + (size_t)h * half);

            float s[4] = {0.f, 0.f, 0.f, 0.f};
            float c[4] = {0.f, 0.f, 0.f, 0.f};
            for (int i = 0; i < nq; i++) {
                float4 xvv = xr[i];
                float4 wvv = wr[i];
                float a4[4] = {xvv.x, xvv.y, xvv.z, xvv.w};
                float b4[4] = {wvv.x, wvv.y, wvv.z, wvv.w};
                #pragma unroll
                for (int l = 0; l < 4; l++) {
                    float p  = a4[l] * b4[l];
                    float pe = fmaf(a4[l], b4[l], -p);
                    float t2 = s[l] + p;
                    float z  = t2 - s[l];
                    float er = (s[l] - (t2 - z)) + (p - z);
                    s[l] = t2;
                    c[l] += er + pe;
                }
            }
            double tot = 0.0;
            #pragma unroll
            for (int l = 0; l < 4; l++) tot += (double)s[l] + (double)c[l];
            s_partial[tid] = tot;
            __syncthreads();

            if (h == 0)
                s_logit[e] = s_partial[2 * e] + s_partial[2 * e + 1] + (double)bias[e];
            __syncthreads();

            if (tid == 0) {
                double tv[4] = {-1e300, -1e300, -1e300, -1e300};
                int    ti[4] = {0, 0, 0, 0};
                for (int k = 0; k < 128; k++) {
                    double val = s_logit[k];
                    if (val > tv[3]) {
                        tv[3] = val; ti[3] = k;
                        #pragma unroll
                        for (int s2 = 3; s2 > 0; s2--) {
                            if (tv[s2] > tv[s2 - 1]) {
                                double fv = tv[s2]; tv[s2] = tv[s2-1]; tv[s2-1] = fv;
                                int    fi = ti[s2]; ti[s2] = ti[s2-1]; ti[s2-1] = fi;
                            }
                        }
                    }
                }
                float v0 = (float)tv[0], v1 = (float)tv[1],
                      v2 = (float)tv[2], v3 = (float)tv[3];
                float e0 = expf(v0 - v0);
                float e1 = expf(v1 - v0);
                float e2 = expf(v2 - v0);
                float e3 = expf(v3 - v0);
                float inv = 1.0f / (e0 + e1 + e2 + e3);
                out_vals[(size_t)token * 4 + 0] = e0 * inv;
                out_vals[(size_t)token * 4 + 1] = e1 * inv;
                out_vals[(size_t)token * 4 + 2] = e2 * inv;
                out_vals[(size_t)token * 4 + 3] = e3 * inv;
                out_idx[(size_t)token * 4 + 0] = (float)ti[0];
                out_idx[(size_t)token * 4 + 1] = (float)ti[1];
                out_idx[(size_t)token * 4 + 2] = (float)ti[2];
                out_idx[(size_t)token * 4 + 3] = (float)ti[3];
            }
            __syncthreads();
        }
    }

    // last finishing block resets the worklist for the next graph replay
    __syncthreads();
    if (threadIdx.x == 0) {
        const int d = atomicAdd(&g_done, 1);
        if (d == (int)gridDim.x - 1) {
            g_count = 0;
            g_done  = 0;
        }
    }
}

extern "C" void kernel_launch(void* const* d_in, const int* in_sizes, int n_in,
                              void* d_out, int out_size)
{
    const float* X    = (const float*)d_in[0];
    const float* W    = (const float*)d_in[1];
    const float* bias = (const float*)d_in[2];

    const int E = in_sizes[2];          // 128
    const int H = in_sizes[1] / E;      // 2880
    const int T = in_sizes[0] / H;      // 16384

    float* out        = (float*)d_out;
    float* out_vals   = out;
    float* out_idx    = out + (size_t)T * 4;
    float* out_logits = out + (size_t)T * 8;

    cudaFuncSetAttribute(gemm_kernel,
                         cudaFuncAttributeMaxDynamicSharedMemorySize,
                         SMEM_TOTAL);

    const int nchunks = (H / 32) * 512;            // 46080
    wcvt_kernel<<<(nchunks + 255) / 256, 256>>>(W, H);
    gemm_kernel<<<T / BM, NTHREADS, SMEM_TOTAL>>>(
        X, bias, out_vals, out_idx, out_logits, T, H);
    refine_kernel<<<2048, 256>>>(X, W, bias, out_vals, out_idx, T, H);
}